// round 14
// baseline (speedup 1.0000x reference)
#include <cuda_runtime.h>
#include <cuda_fp16.h>

#define NN      512
#define MM      512
#define NB      32
#define NBLK    16
#define TILE_H  (MM * NB)      // 16384 halves = 32 KB per tile
#define TPB     512
#define NPROB   256
#define NRES    208            // problems with L2-resident (evict_last) tiles
#define C_ALPHA 0.005f
#define C_SCALE 0.001f
#define C_DELTA 0.1f
#define MAX_UPD 51

// Retiled A (fp16): [prob][tile j][512 rows x 32 cols], row=64B=4 segs of 16B,
// swizzle: logical seg s stored at phys = s ^ ((r>>1)&3).
__device__ __half d_At[(size_t)NPROB * NN * MM];

__device__ __forceinline__ void cp_async16_pol(void* dst_smem, const void* src_gmem,
                                               unsigned long long pol) {
    unsigned d = (unsigned)__cvta_generic_to_shared(dst_smem);
    asm volatile("cp.async.cg.shared.global.L2::cache_hint [%0], [%1], 16, %2;"
                 :: "r"(d), "l"(src_gmem), "l"(pol));
}
__device__ __forceinline__ void cp_commit() { asm volatile("cp.async.commit_group;"); }
__device__ __forceinline__ void cp_wait0()  { asm volatile("cp.async.wait_group 0;"); }
__device__ __forceinline__ void cp_wait1()  { asm volatile("cp.async.wait_group 1;"); }

// ---------------- retile + quantize: fp32 row-major -> fp16 swizzled 32KB tiles ----------
__global__ __launch_bounds__(TPB)
void retile_kernel(const float* __restrict__ Ain) {
    const int p   = blockIdx.x;
    const int tid = threadIdx.x;
    const float* Ap = Ain + (size_t)p * (MM * NN);
    __half* Tp = d_At + (size_t)p * (MM * NN);

    __shared__ __half st[16 * 1024];   // 16 tiles x (32 rows x 32 cols) staged

    for (int rb = 0; rb < 16; rb++) {
#pragma unroll
        for (int i = 0; i < 4; i++) {
            int lin  = i * TPB + tid;
            int rr   = lin >> 6;
            int segi = lin & 63;
            int j    = segi >> 2;
            int s    = segi & 3;
            int r    = rb * 32 + rr;
            const float4* src = (const float4*)(Ap + (size_t)r * NN + j * NB + s * 8);
            float4 a = src[0], b = src[1];
            int phys = s ^ ((r >> 1) & 3);
            __half2* d = (__half2*)(st + j * 1024 + rr * NB + phys * 8);
            d[0] = __floats2half2_rn(a.x, a.y);
            d[1] = __floats2half2_rn(a.z, a.w);
            d[2] = __floats2half2_rn(b.x, b.y);
            d[3] = __floats2half2_rn(b.z, b.w);
        }
        __syncthreads();
#pragma unroll
        for (int i = 0; i < 4; i++) {
            int dlin = i * TPB + tid;
            int j = dlin >> 7;
            int u = dlin & 127;
            uint4 v = ((const uint4*)(st + j * 1024))[u];
            ((uint4*)(Tp + (size_t)j * TILE_H + rb * 1024))[u] = v;
        }
        __syncthreads();
    }
}

// ---------------- main kernel ----------------
extern __shared__ __half smh[];

// Warp w loads rows 32w..32w+31 of the tile (2KB), 512B-contiguous per step.
// Safe to issue right after this warp's y-pass read those rows (warp program order).
__device__ __forceinline__ void load_slice(__half* dst, const __half* __restrict__ src,
                                           int wid, int lane, unsigned long long pol) {
    const __half* s = src + wid * 32 * NB + lane * 8;
    __half* d = dst + wid * 32 * NB + lane * 8;
#pragma unroll
    for (int i = 0; i < 4; i++)
        cp_async16_pol(d + i * 256, s + i * 256, pol);
    cp_commit();
}

// fp32 y-pass (initial sweep only)
#define ACCP(u, xv0, xv1) { __half2 _h = *(__half2*)&(u); float2 _f = __half22float2(_h); \
                            yacc = fmaf(_f.x, (xv0), yacc); yacc = fmaf(_f.y, (xv1), yacc); }
#define YSEG(cs, xa, xb) { ACCP((cs).x, (xa).x, (xa).y); ACCP((cs).y, (xa).z, (xa).w); \
                           ACCP((cs).z, (xb).x, (xb).y); ACCP((cs).w, (xb).z, (xb).w); }
#define YPASS32(Abase, xqp) { \
    const float4* xq = (const float4*)(xqp); \
    const uint4* rowp = (const uint4*)((Abase) + tid * NB); \
    _Pragma("unroll") \
    for (int s = 0; s < 4; s++) { \
        uint4 cs = rowp[s ^ q2]; \
        float4 xa = xq[2 * s], xb = xq[2 * s + 1]; \
        YSEG(cs, xa, xb); \
    } }

// fp16 y-pass (iterate sweeps): A half2s * x half2s, two 8-long HFMA2 chains
#define HSEG(acc, au, xu) { acc = __hfma2(*(__half2*)&(au).x, *(__half2*)&(xu).x, acc); \
                            acc = __hfma2(*(__half2*)&(au).y, *(__half2*)&(xu).y, acc); \
                            acc = __hfma2(*(__half2*)&(au).z, *(__half2*)&(xu).z, acc); \
                            acc = __hfma2(*(__half2*)&(au).w, *(__half2*)&(xu).w, acc); }
#define YPASSH(Abase, xhp) { \
    const uint4* xh = (const uint4*)(xhp); \
    const uint4* rowp = (const uint4*)((Abase) + tid * NB); \
    __half2 acA = __float2half2_rn(0.0f), acB = __float2half2_rn(0.0f); \
    { uint4 au = rowp[0 ^ q2]; uint4 xu = xh[0]; HSEG(acA, au, xu); } \
    { uint4 au = rowp[1 ^ q2]; uint4 xu = xh[1]; HSEG(acB, au, xu); } \
    { uint4 au = rowp[2 ^ q2]; uint4 xu = xh[2]; HSEG(acA, au, xu); } \
    { uint4 au = rowp[3 ^ q2]; uint4 xu = xh[3]; HSEG(acB, au, xu); } \
    float2 fa = __half22float2(acA); float2 fb = __half22float2(acB); \
    yacc += (fa.x + fa.y) + (fb.x + fb.y); }

__global__ __launch_bounds__(TPB, 2)
void lva_kernel(const float* __restrict__ xin,
                const float* __restrict__ bin,
                float* __restrict__ xout) {
    const int p    = blockIdx.x;
    const int tid  = threadIdx.x;
    const int wid  = tid >> 5;
    const int lane = tid & 31;

    __half* sA[3];
    sA[0] = smh;
    sA[1] = sA[0] + TILE_H;
    sA[2] = sA[1] + TILE_H;
    float* sx    = (float*)(sA[2] + TILE_H);   // 512
    float* sviol = sx + NN;                    // 512
    float* spart = sviol + MM;                 // 2048 (double-buffered [2][32 phases][32 cols])
    float* sred  = spart + 2048;               // 32
    __half* sxh  = (__half*)(sred + 32);       // 64 (double-buffered fp16 x-block)

    const __half* Tp = d_At + (size_t)p * (MM * NN);

    unsigned long long pol;
    if (p < NRES)
        asm("createpolicy.fractional.L2::evict_last.b64 %0, 1.0;" : "=l"(pol));
    else
        asm("createpolicy.fractional.L2::evict_first.b64 %0, 1.0;" : "=l"(pol));

    sx[tid] = xin[p * NN + tid];
    const float breg = bin[p * MM + tid];
    __syncthreads();

    load_slice(sA[0], Tp, wid, lane, pol);
    load_slice(sA[1], Tp + TILE_H, wid, lane, pol);
    unsigned gl = 2;       // next tile to issue (tile gl&15, buffer gl%3)
    unsigned gcnt = 0;     // tiles consumed

    const int q2   = (tid >> 1) & 3;          // y-pass swizzle key (row = tid)
    const int c2   = tid & 15;                // g-pass column pair
    const int krow = tid >> 4;                // g-pass row phase (0..31)
    const int goff = krow * NB + (((c2 >> 2) ^ ((krow >> 1) & 3)) << 3) + ((c2 & 3) << 1);

    __half2 vr2[16];                          // duplicated viol (fp16) for g-pass
    float yacc = 0.0f;

    // ---------- initial sweep: y = A @ x (fp32), 2-ahead prefetch ----------
    for (int j = 0; j < NBLK; j++) {
        cp_wait1();
        __syncthreads();
        const __half* A = sA[gcnt % 3];
        YPASS32(A, sx + j * NB);
        load_slice(sA[gl % 3], Tp + (size_t)(gl & 15) * TILE_H, wid, lane, pol);
        gl++; gcnt++;
    }
    // invariant here: gl = gcnt + 2; tiles 0',1' of next sweep in flight

    // ---------- finalize ----------
    float total;
    {
        float v = fmaxf(__fadd_rn(yacc, -breg), 0.0f);
        sviol[tid] = v;
        float t = v;
#pragma unroll
        for (int o = 16; o > 0; o >>= 1) t += __shfl_down_sync(0xffffffffu, t, o);
        if ((tid & 31) == 0) sred[tid >> 5] = t;
        __syncthreads();
        if (tid < 32) {
            float w = (tid < 16) ? sred[tid] : 0.0f;
#pragma unroll
            for (int o = 8; o > 0; o >>= 1) w += __shfl_down_sync(0xffffffffu, w, o);
            if (tid == 0) sred[16] = w;
        }
        __syncthreads();
        total = sred[16];
#pragma unroll
        for (int i = 0; i < 16; i++)
            vr2[i] = __half2half2(__float2half_rn(sviol[krow + 32 * i]));
        yacc = 0.0f;
    }

    // ---------- iterate: ONE barrier per block ----------
    // phase j: [wait; bar] { g(j) || upd(j-1)[warp15] || y(j-2) || prefetch(j+1) }
    int it = 0;
    while (it < MAX_UPD && total >= C_DELTA) {
        const bool last = (it == MAX_UPD - 1);

        for (int j = 0; j < NBLK; j++) {
            if (j == 0) cp_wait1(); else cp_wait0();
            __syncthreads();
            const __half* A = sA[gcnt % 3];           // tile j

            // g(j) -> spart buffer j&1
            {
                float* sp = spart + (j & 1) * 1024;
                const __half2* ap = (const __half2*)(A + goff);
                __half2 acc2 = __float2half2_rn(0.0f);
#pragma unroll
                for (int i = 0; i < 16; i++)
                    acc2 = __hfma2(vr2[i], ap[i * 512], acc2);
                float2 gf = __half22float2(acc2);
                sp[krow * NB + 2 * c2]     = gf.x;
                sp[krow * NB + 2 * c2 + 1] = gf.y;
            }

            // upd(j-1): warp 15, reads spart (j-1)&1 (fenced by top barrier)
            if (wid == 15 && j >= 1) {
                const float* spo = spart + ((j - 1) & 1) * 1024;
                float g0 = 0.0f, g1 = 0.0f;
#pragma unroll
                for (int k = 0; k < 16; k++) {
                    g0 += spo[(2 * k) * NB + lane];
                    g1 += spo[(2 * k + 1) * NB + lane];
                }
                float g   = g0 + g1;
                float xo  = sx[(j - 1) * NB + lane];
                float den = __fadd_rn(1.0f, __fmul_rn(C_SCALE, g));
                float lr  = __fdiv_rn(C_ALPHA, den);
                float xn  = fmaxf(__fsub_rn(xo, __fmul_rn(lr, g)), 0.0f);
                sx[(j - 1) * NB + lane] = xn;
                sxh[((j - 1) & 1) * NB + lane] = __float2half_rn(xn);
            }

            // y(j-2): tile buffer (gcnt+1)%3, x' in sxh buffer (j-2)&1 == j&1
            if (!last && j >= 2) {
                const __half* Ay = sA[(gcnt + 1) % 3];
                YPASSH(Ay, sxh + (j & 1) * NB);
            }

            // prefetch tile j+1 into the buffer y(j-2) just released (warp-order safe)
            if (j >= 1) {
                load_slice(sA[gl % 3], Tp + (size_t)(gl & 15) * TILE_H, wid, lane, pol);
                gl++;
            }
            gcnt++;
        }

        // epilogue A: upd(15) || y(14) ; prefetch tile 1'
        __syncthreads();
        if (wid == 15) {
            const float* spo = spart + 1024;          // 15&1 = 1
            float g0 = 0.0f, g1 = 0.0f;
#pragma unroll
            for (int k = 0; k < 16; k++) {
                g0 += spo[(2 * k) * NB + lane];
                g1 += spo[(2 * k + 1) * NB + lane];
            }
            float g   = g0 + g1;
            float xo  = sx[15 * NB + lane];
            float den = __fadd_rn(1.0f, __fmul_rn(C_SCALE, g));
            float lr  = __fdiv_rn(C_ALPHA, den);
            float xn  = fmaxf(__fsub_rn(xo, __fmul_rn(lr, g)), 0.0f);
            sx[15 * NB + lane] = xn;
            sxh[NB + lane] = __float2half_rn(xn);     // buffer 1
        }
        if (!last) {
            YPASSH(sA[(gcnt + 1) % 3], sxh + 0 * NB); // y(14): tile14, sxh buf 0
            load_slice(sA[gl % 3], Tp + (size_t)(gl & 15) * TILE_H, wid, lane, pol);
            gl++;                                      // restores gl = gcnt + 2
        }

        if (last) { __syncthreads(); break; }          // x complete; skip y(15)/finalize

        // epilogue B: y(15)
        __syncthreads();
        YPASSH(sA[(gcnt + 2) % 3], sxh + NB);          // tile15, sxh buf 1

        // finalize
        {
            float v = fmaxf(__fadd_rn(yacc, -breg), 0.0f);
            sviol[tid] = v;
            float t = v;
#pragma unroll
            for (int o = 16; o > 0; o >>= 1) t += __shfl_down_sync(0xffffffffu, t, o);
            if ((tid & 31) == 0) sred[tid >> 5] = t;
            __syncthreads();
            if (tid < 32) {
                float w = (tid < 16) ? sred[tid] : 0.0f;
#pragma unroll
                for (int o = 8; o > 0; o >>= 1) w += __shfl_down_sync(0xffffffffu, w, o);
                if (tid == 0) sred[16] = w;
            }
            __syncthreads();
            total = sred[16];
#pragma unroll
            for (int i = 0; i < 16; i++)
                vr2[i] = __half2half2(__float2half_rn(sviol[krow + 32 * i]));
            yacc = 0.0f;
        }
        it++;
    }

    cp_wait0();   // drain outstanding speculative loads
    xout[p * NN + tid] = sx[tid];
}

extern "C" void kernel_launch(void* const* d_in, const int* in_sizes, int n_in,
                              void* d_out, int out_size) {
    // metadata order: x [B,S,N], A [B,S,M,N], b [B,S,M]
    const float* x = (const float*)d_in[0];
    const float* A = (const float*)d_in[1];
    const float* b = (const float*)d_in[2];
    float* out = (float*)d_out;

    if (n_in == 3 && in_sizes[0] > in_sizes[1]) {
        A = (const float*)d_in[0];
        x = (const float*)d_in[1];
    }

    int nprob = out_size / NN;   // 256

    retile_kernel<<<nprob, TPB>>>(A);

    size_t smem_bytes = (size_t)(3 * TILE_H) * sizeof(__half)
                      + (size_t)(NN + MM + 2048 + 32) * sizeof(float)
                      + 64 * sizeof(__half);
    cudaFuncSetAttribute(lva_kernel, cudaFuncAttributeMaxDynamicSharedMemorySize,
                         (int)smem_bytes);
    lva_kernel<<<nprob, TPB, smem_bytes>>>(x, b, out);
}

// round 15
// speedup vs baseline: 1.2437x; 1.2437x over previous
#include <cuda_runtime.h>
#include <cuda_fp16.h>

#define NN      512
#define MM      512
#define NB      32
#define NBLK    16
#define TILE_H  (MM * NB)      // 16384 halves = 32 KB per tile
#define TPB     512
#define NPROB   256
#define NRES    208            // problems with L2-resident (evict_last) tiles
#define C_ALPHA 0.005f
#define C_SCALE 0.001f
#define C_DELTA 0.1f
#define MAX_UPD 51

// Retiled A (fp16): [prob][tile j][512 rows x 32 cols], row=64B=4 segs of 16B,
// swizzle: logical seg s stored at phys = s ^ ((r>>1)&3).
__device__ __half d_At[(size_t)NPROB * NN * MM];
// Initial y0 = A @ x0 (computed by retile kernel, fp32)
__device__ float  d_y0[(size_t)NPROB * MM];

__device__ __forceinline__ void cp_async16_pol(void* dst_smem, const void* src_gmem,
                                               unsigned long long pol) {
    unsigned d = (unsigned)__cvta_generic_to_shared(dst_smem);
    asm volatile("cp.async.cg.shared.global.L2::cache_hint [%0], [%1], 16, %2;"
                 :: "r"(d), "l"(src_gmem), "l"(pol));
}
__device__ __forceinline__ void cp_commit() { asm volatile("cp.async.commit_group;"); }
__device__ __forceinline__ void cp_wait0()  { asm volatile("cp.async.wait_group 0;"); }
__device__ __forceinline__ void cp_wait1()  { asm volatile("cp.async.wait_group 1;"); }

// ---------- retile + quantize + initial Ax: fp32 row-major -> fp16 tiles + d_y0 ----------
__global__ __launch_bounds__(TPB)
void retile_kernel(const float* __restrict__ Ain, const float* __restrict__ xin) {
    const int p    = blockIdx.x;
    const int tid  = threadIdx.x;
    const int wid  = tid >> 5;
    const int lane = tid & 31;
    const float* Ap = Ain + (size_t)p * (MM * NN);
    __half* Tp = d_At + (size_t)p * (MM * NN);

    __shared__ __half st[16 * 1024];   // 16 tiles x (32 rows x 32 cols) staged
    __shared__ float  sxr[NN];         // x0 staged
    __shared__ float  sacc[64];        // per-(row-in-group, warp-parity) dot partials

    sxr[tid] = xin[p * NN + tid];
    __syncthreads();

    for (int rb = 0; rb < 16; rb++) {
        // Phase A: coalesced fp32 reads -> fp16 swizzled smem + dot partials
#pragma unroll
        for (int i = 0; i < 4; i++) {
            int lin  = i * TPB + tid;
            int rr   = lin >> 6;               // row in group (warp-uniform per i)
            int segi = lin & 63;
            int j    = segi >> 2;
            int s    = segi & 3;
            int r    = rb * 32 + rr;
            const float4* src = (const float4*)(Ap + (size_t)r * NN + j * NB + s * 8);
            float4 a = src[0], b = src[1];
            int phys = s ^ ((r >> 1) & 3);
            __half2* d = (__half2*)(st + j * 1024 + rr * NB + phys * 8);
            d[0] = __floats2half2_rn(a.x, a.y);
            d[1] = __floats2half2_rn(a.z, a.w);
            d[2] = __floats2half2_rn(b.x, b.y);
            d[3] = __floats2half2_rn(b.z, b.w);

            // dot partial with x[segi*8 .. segi*8+7]
            const float4* xv = (const float4*)(sxr + segi * 8);
            float4 x0 = xv[0], x1 = xv[1];
            float pd = a.x * x0.x + a.y * x0.y + a.z * x0.z + a.w * x0.w
                     + b.x * x1.x + b.y * x1.y + b.z * x1.z + b.w * x1.w;
#pragma unroll
            for (int o = 16; o > 0; o >>= 1) pd += __shfl_down_sync(0xffffffffu, pd, o);
            if (lane == 0) sacc[rr * 2 + (wid & 1)] = pd;  // single writer per slot
        }
        __syncthreads();
        // finalize this group's y0 (32 threads) — reads sacc before next overwrite
        if ((tid >> 5) == rb) {
            int rr = tid & 31;
            d_y0[(size_t)p * MM + rb * 32 + rr] = sacc[rr * 2] + sacc[rr * 2 + 1];
        }
        // Phase B: contiguous 2KB-per-tile chunk writes
#pragma unroll
        for (int i = 0; i < 4; i++) {
            int dlin = i * TPB + tid;
            int j = dlin >> 7;
            int u = dlin & 127;
            uint4 v = ((const uint4*)(st + j * 1024))[u];
            ((uint4*)(Tp + (size_t)j * TILE_H + rb * 1024))[u] = v;
        }
        __syncthreads();
    }
}

// ---------------- main kernel ----------------
extern __shared__ __half smh[];

__device__ __forceinline__ void load_tile(__half* dst, const __half* __restrict__ src,
                                          int tid, unsigned long long pol) {
#pragma unroll
    for (int i = 0; i < 4; i++) {
        int lin = i * TPB + tid;
        cp_async16_pol(dst + lin * 8, src + lin * 8, pol);
    }
    cp_commit();
}

// fp16 y-pass: A half2s * x half2s, two 8-long HFMA2 chains
#define HSEG(acc, au, xu) { acc = __hfma2(*(__half2*)&(au).x, *(__half2*)&(xu).x, acc); \
                            acc = __hfma2(*(__half2*)&(au).y, *(__half2*)&(xu).y, acc); \
                            acc = __hfma2(*(__half2*)&(au).z, *(__half2*)&(xu).z, acc); \
                            acc = __hfma2(*(__half2*)&(au).w, *(__half2*)&(xu).w, acc); }
#define YPASSH(Abase) { \
    const uint4* xh = (const uint4*)sxh; \
    const uint4* rowp = (const uint4*)((Abase) + tid * NB); \
    __half2 acA = __float2half2_rn(0.0f), acB = __float2half2_rn(0.0f); \
    { uint4 au = rowp[0 ^ q2]; uint4 xu = xh[0]; HSEG(acA, au, xu); } \
    { uint4 au = rowp[1 ^ q2]; uint4 xu = xh[1]; HSEG(acB, au, xu); } \
    { uint4 au = rowp[2 ^ q2]; uint4 xu = xh[2]; HSEG(acA, au, xu); } \
    { uint4 au = rowp[3 ^ q2]; uint4 xu = xh[3]; HSEG(acB, au, xu); } \
    float2 fa = __half22float2(acA); float2 fb = __half22float2(acB); \
    yacc += (fa.x + fa.y) + (fb.x + fb.y); }

// single-barrier finalize: viol store, warp sums, one bar, every thread sums 16 partials
#define FINALIZE() { \
    float v = fmaxf(__fadd_rn(yacc, -breg), 0.0f); \
    sviol[tid] = v; \
    float t = v; \
    _Pragma("unroll") \
    for (int o = 16; o > 0; o >>= 1) t += __shfl_down_sync(0xffffffffu, t, o); \
    if ((tid & 31) == 0) sred[tid >> 5] = t; \
    __syncthreads(); \
    total = 0.0f; \
    _Pragma("unroll") \
    for (int k = 0; k < 16; k++) total += sred[k]; \
    _Pragma("unroll") \
    for (int i = 0; i < 16; i++) \
        vr2[i] = __half2half2(__float2half_rn(sviol[krow + 32 * i])); \
    yacc = 0.0f; }

__global__ __launch_bounds__(TPB, 2)
void lva_kernel(const float* __restrict__ xin,
                const float* __restrict__ bin,
                float* __restrict__ xout) {
    const int p   = blockIdx.x;
    const int tid = threadIdx.x;

    __half* sA[3];
    sA[0] = smh;
    sA[1] = sA[0] + TILE_H;
    sA[2] = sA[1] + TILE_H;
    float* sx    = (float*)(sA[2] + TILE_H);   // 512
    float* sviol = sx + NN;                    // 512
    float* spart = sviol + MM;                 // 1024 ([32 phases][32 cols])
    float* sred  = spart + 1024;               // 32
    __half* sxh  = (__half*)(sred + 32);       // 32 halves (fp16 broadcast of x-block)

    const __half* Tp = d_At + (size_t)p * (MM * NN);

    unsigned long long pol;
    if (p < NRES)
        asm("createpolicy.fractional.L2::evict_last.b64 %0, 1.0;" : "=l"(pol));
    else
        asm("createpolicy.fractional.L2::evict_first.b64 %0, 1.0;" : "=l"(pol));

    sx[tid] = xin[p * NN + tid];
    const float breg = bin[p * MM + tid];

    load_tile(sA[0], Tp, tid, pol);
    load_tile(sA[1], Tp + TILE_H, tid, pol);
    unsigned gl = 2;       // next tile to issue (buffer gl%3, tile gl&15)
    unsigned gcnt = 0;     // tiles consumed

    const int q2   = (tid >> 1) & 3;          // y-pass swizzle key (row = tid)
    const int c2   = tid & 15;                // g-pass column pair
    const int krow = tid >> 4;                // g-pass row phase (0..31)
    const int goff = krow * NB + (((c2 >> 2) ^ ((krow >> 1) & 3)) << 3) + ((c2 & 3) << 1);

    __half2 vr2[16];                          // duplicated viol (fp16) for g-pass
    float yacc = d_y0[(size_t)p * MM + tid];  // initial Ax from retile kernel
    float total;

    __syncthreads();                          // sx visible (and smem layout settled)
    FINALIZE();                               // initial viol/total/vr2 from y0

    // ---------- iterate: per block [bar] {g(j) || y(j-1)} [bar] {prefetch; upd(j)} ----------
    int it = 0;
    while (it < MAX_UPD && total >= C_DELTA) {
        const bool last = (it == MAX_UPD - 1);
        const __half* Aprev = sA[0];   // dummy init; unused at j=0

        for (int j = 0; j < NBLK; j++) {
            cp_wait1();
            __syncthreads();           // tile j ready; upd(j-1) visible
            const __half* A = sA[gcnt % 3];

            // g(j): colpair (2c2,2c2+1), rows krow+32i (fp16 accumulate)
            {
                const __half2* ap = (const __half2*)(A + goff);  // stride 512 half2 per i
                __half2 acc2 = __float2half2_rn(0.0f);
#pragma unroll
                for (int i = 0; i < 16; i++)
                    acc2 = __hfma2(vr2[i], ap[i * 512], acc2);
                float2 gf = __half22float2(acc2);
                spart[krow * NB + 2 * c2]     = gf.x;
                spart[krow * NB + 2 * c2 + 1] = gf.y;
            }

            // y(j-1): yacc += Aprev[tid,:] . x'(block j-1)   (skipped on last sweep)
            if (j > 0 && !last) YPASSH(Aprev);
            __syncthreads();           // g partials complete; tile j-1 free; sxh consumed

            // phase2: prefetch tile gl (into tile j-1's buffer) + update x(block j)
            load_tile(sA[gl % 3], Tp + (size_t)(gl & 15) * TILE_H, tid, pol); gl++;
            if (tid < NB) {
                float g0 = 0.0f, g1 = 0.0f;
#pragma unroll
                for (int k = 0; k < 16; k++) {
                    g0 += spart[(2 * k) * NB + tid];
                    g1 += spart[(2 * k + 1) * NB + tid];
                }
                float g   = g0 + g1;
                float xo  = sx[j * NB + tid];
                float den = __fadd_rn(1.0f, __fmul_rn(C_SCALE, g));
                float lr  = __fdiv_rn(C_ALPHA, den);
                float xn  = fmaxf(__fsub_rn(xo, __fmul_rn(lr, g)), 0.0f);
                sx[j * NB + tid] = xn;
                sxh[tid] = __float2half_rn(xn);
            }
            Aprev = A; gcnt++;
        }

        if (last) break;               // x fully updated; y/finalize results unused

        __syncthreads();               // upd(15) visible
        YPASSH(Aprev);                 // y(15)
        FINALIZE();
        it++;
    }

    cp_wait0();                        // drain outstanding speculative loads
    __syncthreads();                   // all sx writes visible
    xout[p * NN + tid] = sx[tid];
}

extern "C" void kernel_launch(void* const* d_in, const int* in_sizes, int n_in,
                              void* d_out, int out_size) {
    // metadata order: x [B,S,N], A [B,S,M,N], b [B,S,M]
    const float* x = (const float*)d_in[0];
    const float* A = (const float*)d_in[1];
    const float* b = (const float*)d_in[2];
    float* out = (float*)d_out;

    if (n_in == 3 && in_sizes[0] > in_sizes[1]) {   // defensive: A is the big one
        A = (const float*)d_in[0];
        x = (const float*)d_in[1];
    }

    int nprob = out_size / NN;   // 256

    retile_kernel<<<nprob, TPB>>>(A, x);

    size_t smem_bytes = (size_t)(3 * TILE_H) * sizeof(__half)
                      + (size_t)(NN + MM + 1024 + 32) * sizeof(float)
                      + 64 * sizeof(__half);
    cudaFuncSetAttribute(lva_kernel, cudaFuncAttributeMaxDynamicSharedMemorySize,
                         (int)smem_bytes);
    lva_kernel<<<nprob, TPB, smem_bytes>>>(x, b, out);
}

// round 16
// speedup vs baseline: 1.2893x; 1.0366x over previous
#include <cuda_runtime.h>
#include <cuda_fp16.h>

#define NN      512
#define MM      512
#define NB      32
#define NBLK    16
#define TILE_H  (MM * NB)      // 16384 halves = 32 KB per tile
#define TPB     512
#define NPROB   256
#define NRES    208            // problems with L2-resident (evict_last) tiles
#define C_ALPHA 0.005f
#define C_SCALE 0.001f
#define C_DELTA 0.1f
#define MAX_UPD 51

// Retiled A (fp16): [prob][tile j][512 rows x 32 cols], row=64B=4 segs of 16B,
// swizzle: logical seg s stored at phys = s ^ ((r>>1)&3).
__device__ __half d_At[(size_t)NPROB * NN * MM];

__device__ __forceinline__ void cp_async16_pol(void* dst_smem, const void* src_gmem,
                                               unsigned long long pol) {
    unsigned d = (unsigned)__cvta_generic_to_shared(dst_smem);
    asm volatile("cp.async.cg.shared.global.L2::cache_hint [%0], [%1], 16, %2;"
                 :: "r"(d), "l"(src_gmem), "l"(pol));
}
__device__ __forceinline__ void cp_commit() { asm volatile("cp.async.commit_group;"); }
__device__ __forceinline__ void cp_wait0()  { asm volatile("cp.async.wait_group 0;"); }
__device__ __forceinline__ void cp_wait1()  { asm volatile("cp.async.wait_group 1;"); }

// ---------------- retile + quantize: fp32 row-major -> fp16 swizzled 32KB tiles ----------
__global__ __launch_bounds__(TPB)
void retile_kernel(const float* __restrict__ Ain) {
    const int p   = blockIdx.x;
    const int tid = threadIdx.x;
    const float* Ap = Ain + (size_t)p * (MM * NN);
    __half* Tp = d_At + (size_t)p * (MM * NN);

    __shared__ __half st[16 * 1024];   // 16 tiles x (32 rows x 32 cols) staged

    for (int rb = 0; rb < 16; rb++) {
#pragma unroll
        for (int i = 0; i < 4; i++) {
            int lin  = i * TPB + tid;
            int rr   = lin >> 6;
            int segi = lin & 63;
            int j    = segi >> 2;
            int s    = segi & 3;
            int r    = rb * 32 + rr;
            const float4* src = (const float4*)(Ap + (size_t)r * NN + j * NB + s * 8);
            float4 a = src[0], b = src[1];
            int phys = s ^ ((r >> 1) & 3);
            __half2* d = (__half2*)(st + j * 1024 + rr * NB + phys * 8);
            d[0] = __floats2half2_rn(a.x, a.y);
            d[1] = __floats2half2_rn(a.z, a.w);
            d[2] = __floats2half2_rn(b.x, b.y);
            d[3] = __floats2half2_rn(b.z, b.w);
        }
        __syncthreads();
#pragma unroll
        for (int i = 0; i < 4; i++) {
            int dlin = i * TPB + tid;
            int j = dlin >> 7;
            int u = dlin & 127;
            uint4 v = ((const uint4*)(st + j * 1024))[u];
            ((uint4*)(Tp + (size_t)j * TILE_H + rb * 1024))[u] = v;
        }
        __syncthreads();
    }
}

// ---------------- main kernel ----------------
extern __shared__ __half smh[];

__device__ __forceinline__ void load_tile(__half* dst, const __half* __restrict__ src,
                                          int tid, unsigned long long pol) {
#pragma unroll
    for (int i = 0; i < 4; i++) {
        int lin = i * TPB + tid;
        cp_async16_pol(dst + lin * 8, src + lin * 8, pol);
    }
    cp_commit();
}

// fp32 y-pass (initial sweep only)
#define ACCP(u, xv0, xv1) { __half2 _h = *(__half2*)&(u); float2 _f = __half22float2(_h); \
                            yacc = fmaf(_f.x, (xv0), yacc); yacc = fmaf(_f.y, (xv1), yacc); }
#define YSEG(cs, xa, xb) { ACCP((cs).x, (xa).x, (xa).y); ACCP((cs).y, (xa).z, (xa).w); \
                           ACCP((cs).z, (xb).x, (xb).y); ACCP((cs).w, (xb).z, (xb).w); }
#define YPASS32(Abase, xqp) { \
    const float4* xq = (const float4*)(xqp); \
    const uint4* rowp = (const uint4*)((Abase) + tid * NB); \
    _Pragma("unroll") \
    for (int s = 0; s < 4; s++) { \
        uint4 cs = rowp[s ^ q2]; \
        float4 xa = xq[2 * s], xb = xq[2 * s + 1]; \
        YSEG(cs, xa, xb); \
    } }

// fp16 y-pass (iterate sweeps): A half2s * x half2s, two 8-long HFMA2 chains
#define HSEG(acc, au, xu) { acc = __hfma2(*(__half2*)&(au).x, *(__half2*)&(xu).x, acc); \
                            acc = __hfma2(*(__half2*)&(au).y, *(__half2*)&(xu).y, acc); \
                            acc = __hfma2(*(__half2*)&(au).z, *(__half2*)&(xu).z, acc); \
                            acc = __hfma2(*(__half2*)&(au).w, *(__half2*)&(xu).w, acc); }
#define YPASSH(Abase) { \
    const uint4* xh = (const uint4*)sxh; \
    const uint4* rowp = (const uint4*)((Abase) + tid * NB); \
    __half2 acA = __float2half2_rn(0.0f), acB = __float2half2_rn(0.0f); \
    { uint4 au = rowp[0 ^ q2]; uint4 xu = xh[0]; HSEG(acA, au, xu); } \
    { uint4 au = rowp[1 ^ q2]; uint4 xu = xh[1]; HSEG(acB, au, xu); } \
    { uint4 au = rowp[2 ^ q2]; uint4 xu = xh[2]; HSEG(acA, au, xu); } \
    { uint4 au = rowp[3 ^ q2]; uint4 xu = xh[3]; HSEG(acB, au, xu); } \
    float2 fa = __half22float2(acA); float2 fb = __half22float2(acB); \
    yacc += (fa.x + fa.y) + (fb.x + fb.y); }

// g-pass: 2 independent HFMA2 chains (even/odd i)
#define GPASS(A, sp) { \
    const __half2* ap = (const __half2*)((A) + goff); \
    __half2 a0 = __float2half2_rn(0.0f), a1 = __float2half2_rn(0.0f); \
    _Pragma("unroll") \
    for (int i = 0; i < 8; i++) { \
        a0 = __hfma2(vr2[2 * i],     ap[(2 * i) * 512],     a0); \
        a1 = __hfma2(vr2[2 * i + 1], ap[(2 * i + 1) * 512], a1); \
    } \
    float2 gf = __half22float2(__hadd2(a0, a1)); \
    (sp)[krow * NB + 2 * c2]     = gf.x; \
    (sp)[krow * NB + 2 * c2 + 1] = gf.y; }

// x update for block j (threads tid<NB), 4 partial sums
#define UPDATE(j) { \
    float g0 = 0.0f, g1 = 0.0f, g2 = 0.0f, g3 = 0.0f; \
    _Pragma("unroll") \
    for (int k = 0; k < 8; k++) { \
        g0 += spart[(4 * k) * NB + tid]; \
        g1 += spart[(4 * k + 1) * NB + tid]; \
        g2 += spart[(4 * k + 2) * NB + tid]; \
        g3 += spart[(4 * k + 3) * NB + tid]; \
    } \
    float g   = (g0 + g1) + (g2 + g3); \
    float xo  = sx[(j) * NB + tid]; \
    float den = __fadd_rn(1.0f, __fmul_rn(C_SCALE, g)); \
    float lr  = __fdiv_rn(C_ALPHA, den); \
    float xn  = fmaxf(__fsub_rn(xo, __fmul_rn(lr, g)), 0.0f); \
    sx[(j) * NB + tid] = xn; \
    sxh[tid] = __float2half_rn(xn); }

__global__ __launch_bounds__(TPB, 2)
void lva_kernel(const float* __restrict__ xin,
                const float* __restrict__ bin,
                float* __restrict__ xout) {
    const int p   = blockIdx.x;
    const int tid = threadIdx.x;

    __half* sA[3];
    sA[0] = smh;
    sA[1] = sA[0] + TILE_H;
    sA[2] = sA[1] + TILE_H;
    float* sx    = (float*)(sA[2] + TILE_H);   // 512
    float* sviol = sx + NN;                    // 512
    float* spart = sviol + MM;                 // 1024 ([32 phases][32 cols])
    float* sred  = spart + 1024;               // 32
    __half* sxh  = (__half*)(sred + 32);       // 32 halves (fp16 broadcast of x-block)

    const __half* Tp = d_At + (size_t)p * (MM * NN);

    unsigned long long pol;
    if (p < NRES)
        asm("createpolicy.fractional.L2::evict_last.b64 %0, 1.0;" : "=l"(pol));
    else
        asm("createpolicy.fractional.L2::evict_first.b64 %0, 1.0;" : "=l"(pol));

    sx[tid] = xin[p * NN + tid];
    const float breg = bin[p * MM + tid];
    __syncthreads();

    load_tile(sA[0], Tp, tid, pol);
    load_tile(sA[1], Tp + TILE_H, tid, pol);
    unsigned gl = 2;       // next tile to issue (buffer gl%3, tile gl&15)
    unsigned gcnt = 0;     // tiles consumed

    const int q2   = (tid >> 1) & 3;          // y-pass swizzle key (row = tid)
    const int c2   = tid & 15;                // g-pass column pair
    const int krow = tid >> 4;                // g-pass row phase (0..31)
    const int goff = krow * NB + (((c2 >> 2) ^ ((krow >> 1) & 3)) << 3) + ((c2 & 3) << 1);

    __half2 vr2[16];                          // duplicated viol (fp16) for g-pass
    float yacc = 0.0f;

    // ---------- initial sweep: y = A @ x (fp32 x) ----------
    for (int j = 0; j < NBLK; j++) {
        cp_wait1();
        __syncthreads();
        load_tile(sA[gl % 3], Tp + (size_t)(gl & 15) * TILE_H, tid, pol); gl++;
        const __half* A = sA[gcnt % 3]; gcnt++;
        YPASS32(A, sx + j * NB);
    }

    // ---------- finalize ----------
    float total;
    {
        float v = fmaxf(__fadd_rn(yacc, -breg), 0.0f);
        sviol[tid] = v;
        float t = v;
#pragma unroll
        for (int o = 16; o > 0; o >>= 1) t += __shfl_down_sync(0xffffffffu, t, o);
        if ((tid & 31) == 0) sred[tid >> 5] = t;
        __syncthreads();
        if (tid < 32) {
            float w = (tid < 16) ? sred[tid] : 0.0f;
#pragma unroll
            for (int o = 8; o > 0; o >>= 1) w += __shfl_down_sync(0xffffffffu, w, o);
            if (tid == 0) sred[16] = w;
        }
        __syncthreads();
        total = sred[16];
#pragma unroll
        for (int i = 0; i < 16; i++)
            vr2[i] = __half2half2(__float2half_rn(sviol[krow + 32 * i]));
        yacc = 0.0f;
    }

    // ---------- iterate (sweeps 1..50): [bar] {g(j) || y(j-1)} [bar] {prefetch; upd(j)} ----------
    int it = 0;
    while (it < MAX_UPD - 1 && total >= C_DELTA) {
        const __half* Aprev = sA[0];   // dummy init; unused at j=0

        for (int j = 0; j < NBLK; j++) {
            cp_wait1();
            __syncthreads();           // tile j ready; upd(j-1) visible
            const __half* A = sA[gcnt % 3];

            GPASS(A, spart);

            // y(j-1): yacc += Aprev[tid,:] . x'(block j-1)
            if (j > 0) YPASSH(Aprev);
            __syncthreads();           // g partials complete; tile j-1 free; sxh consumed

            // phase2: prefetch + update x(block j)
            load_tile(sA[gl % 3], Tp + (size_t)(gl & 15) * TILE_H, tid, pol); gl++;
            if (tid < NB) UPDATE(j);
            Aprev = A; gcnt++;
        }

        __syncthreads();               // upd(15) visible
        YPASSH(Aprev);                 // y(15)

        // finalize
        {
            float v = fmaxf(__fadd_rn(yacc, -breg), 0.0f);
            sviol[tid] = v;
            float t = v;
#pragma unroll
            for (int o = 16; o > 0; o >>= 1) t += __shfl_down_sync(0xffffffffu, t, o);
            if ((tid & 31) == 0) sred[tid >> 5] = t;
            __syncthreads();
            if (tid < 32) {
                float w = (tid < 16) ? sred[tid] : 0.0f;
#pragma unroll
                for (int o = 8; o > 0; o >>= 1) w += __shfl_down_sync(0xffffffffu, w, o);
                if (tid == 0) sred[16] = w;
            }
            __syncthreads();
            total = sred[16];
#pragma unroll
            for (int i = 0; i < 16; i++)
                vr2[i] = __half2half2(__float2half_rn(sviol[krow + 32 * i]));
            yacc = 0.0f;
        }
        it++;
    }

    // ---------- peeled 51st sweep: update only (y/finalize results are dead) ----------
    if (total >= C_DELTA) {
        for (int j = 0; j < NBLK; j++) {
            cp_wait1();
            __syncthreads();
            const __half* A = sA[gcnt % 3];

            GPASS(A, spart);
            __syncthreads();

            load_tile(sA[gl % 3], Tp + (size_t)(gl & 15) * TILE_H, tid, pol); gl++;
            if (tid < NB) UPDATE(j);
            gcnt++;
        }
        __syncthreads();               // upd(15) visible for output
    }

    cp_wait0();                        // drain outstanding speculative loads
    xout[p * NN + tid] = sx[tid];
}

extern "C" void kernel_launch(void* const* d_in, const int* in_sizes, int n_in,
                              void* d_out, int out_size) {
    // metadata order: x [B,S,N], A [B,S,M,N], b [B,S,M]
    const float* x = (const float*)d_in[0];
    const float* A = (const float*)d_in[1];
    const float* b = (const float*)d_in[2];
    float* out = (float*)d_out;

    if (n_in == 3 && in_sizes[0] > in_sizes[1]) {   // defensive: A is the big one
        A = (const float*)d_in[0];
        x = (const float*)d_in[1];
    }

    int nprob = out_size / NN;   // 256

    retile_kernel<<<nprob, TPB>>>(A);

    size_t smem_bytes = (size_t)(3 * TILE_H) * sizeof(__half)
                      + (size_t)(NN + MM + 1024 + 32) * sizeof(float)
                      + 64 * sizeof(__half);
    cudaFuncSetAttribute(lva_kernel, cudaFuncAttributeMaxDynamicSharedMemorySize,
                         (int)smem_bytes);
    lva_kernel<<<nprob, TPB, smem_bytes>>>(x, b, out);
}

// round 17
// speedup vs baseline: 1.4601x; 1.1325x over previous
#include <cuda_runtime.h>
#include <cuda_fp16.h>

#define NN      512
#define MM      512
#define NB      16            // cols per tile
#define NTILE   32            // tiles per problem
#define NGBLK   16            // tiles per group (half-CTA)
#define TILE_H  (MM * NB)     // 8192 halves = 16 KB
#define TPB     512
#define GSZ     256
#define NPROB   256
#define NRES    208
#define C_ALPHA 0.005f
#define C_SCALE 0.001f
#define C_DELTA 0.1f
#define MAX_UPD 51

// Retiled A (fp16): [prob][tile t][512 rows x 16 cols], row=32B=2 segs of 16B,
// swizzle: logical seg s at phys = s ^ ((r>>2)&1). Tiles contiguous 16KB.
__device__ __half d_At[(size_t)NPROB * NN * MM];

__device__ __forceinline__ void cp_async16_pol(void* dst_smem, const void* src_gmem,
                                               unsigned long long pol) {
    unsigned d = (unsigned)__cvta_generic_to_shared(dst_smem);
    asm volatile("cp.async.cg.shared.global.L2::cache_hint [%0], [%1], 16, %2;"
                 :: "r"(d), "l"(src_gmem), "l"(pol));
}
__device__ __forceinline__ void cp_commit() { asm volatile("cp.async.commit_group;"); }
__device__ __forceinline__ void cp_wait0()  { asm volatile("cp.async.wait_group 0;"); }
__device__ __forceinline__ void cp_wait1()  { asm volatile("cp.async.wait_group 1;"); }

// ---------------- retile: fp32 row-major -> fp16 swizzled 16KB tiles ----------------
__global__ __launch_bounds__(TPB)
void retile_kernel(const float* __restrict__ Ain) {
    const int p   = blockIdx.x;
    const int tid = threadIdx.x;
    const float* Ap = Ain + (size_t)p * (MM * NN);
    __half* Tp = d_At + (size_t)p * (MM * NN);

    __shared__ __half st[16384];   // 32 tiles x (32 rows x 16 halves) staged

    for (int rb = 0; rb < 16; rb++) {
#pragma unroll
        for (int i = 0; i < 4; i++) {
            int lin = i * TPB + tid;           // 16B units, 0..2047
            int rr  = lin >> 6;                // row in group
            int uir = lin & 63;
            int j   = uir >> 1;                // tile 0..31
            int s   = uir & 1;                 // logical seg
            int r   = rb * 32 + rr;
            const float4* src = (const float4*)(Ap + (size_t)r * NN + j * NB + s * 8);
            float4 a = src[0], b = src[1];
            int phys = s ^ ((r >> 2) & 1);
            __half2* d = (__half2*)(st + j * 512 + rr * NB + phys * 8);
            d[0] = __floats2half2_rn(a.x, a.y);
            d[1] = __floats2half2_rn(a.z, a.w);
            d[2] = __floats2half2_rn(b.x, b.y);
            d[3] = __floats2half2_rn(b.z, b.w);
        }
        __syncthreads();
#pragma unroll
        for (int i = 0; i < 4; i++) {
            int dlin = i * TPB + tid;
            int j = dlin >> 6;                 // tile
            int u = dlin & 63;                 // 16B unit in 1KB chunk
            uint4 v = ((const uint4*)(st + j * 512))[u];
            ((uint4*)(Tp + (size_t)j * TILE_H + rb * 512))[u] = v;
        }
        __syncthreads();
    }
}

// ---------------- main kernel ----------------
extern __shared__ __half smh[];

// 16KB tile loaded by this group's 256 threads (contiguous)
__device__ __forceinline__ void load_tile_g(__half* dst, const __half* __restrict__ src,
                                            int tg, unsigned long long pol) {
#pragma unroll
    for (int i = 0; i < 4; i++) {
        int lin = i * GSZ + tg;                // 0..1023 16B units
        cp_async16_pol(dst + lin * 8, src + lin * 8, pol);
    }
    cp_commit();
}

#define GBAR() asm volatile("bar.sync %0, 256;" :: "r"(barid) : "memory")

// fp32 accumulate helpers (initial sweep)
#define ACC32(acc, u, xv0, xv1) { __half2 _h = *(__half2*)&(u); float2 _f = __half22float2(_h); \
                                  (acc) = fmaf(_f.x, (xv0), (acc)); (acc) = fmaf(_f.y, (xv1), (acc)); }
#define YROW32(acc, rbase, xq) { \
    const uint4* rp = (const uint4*)(rbase); \
    { uint4 cs = rp[q];     float4 xa = (xq)[0], xb = (xq)[1]; \
      ACC32(acc, cs.x, xa.x, xa.y); ACC32(acc, cs.y, xa.z, xa.w); \
      ACC32(acc, cs.z, xb.x, xb.y); ACC32(acc, cs.w, xb.z, xb.w); } \
    { uint4 cs = rp[q ^ 1]; float4 xa = (xq)[2], xb = (xq)[3]; \
      ACC32(acc, cs.x, xa.x, xa.y); ACC32(acc, cs.y, xa.z, xa.w); \
      ACC32(acc, cs.z, xb.x, xb.y); ACC32(acc, cs.w, xb.z, xb.w); } }

// fp16 y-pass for one row (iterate sweeps)
#define HSEG(acc, au, xu) { acc = __hfma2(*(__half2*)&(au).x, *(__half2*)&(xu).x, acc); \
                            acc = __hfma2(*(__half2*)&(au).y, *(__half2*)&(xu).y, acc); \
                            acc = __hfma2(*(__half2*)&(au).z, *(__half2*)&(xu).z, acc); \
                            acc = __hfma2(*(__half2*)&(au).w, *(__half2*)&(xu).w, acc); }
#define YROWH(acc, rbase) { \
    const uint4* rp  = (const uint4*)(rbase); \
    const uint4* xh4 = (const uint4*)sxhg; \
    __half2 a2 = __float2half2_rn(0.0f); \
    { uint4 au = rp[q];     uint4 xu = xh4[0]; HSEG(a2, au, xu); } \
    { uint4 au = rp[q ^ 1]; uint4 xu = xh4[1]; HSEG(a2, au, xu); } \
    float2 f2 = __half22float2(a2); \
    (acc) += f2.x + f2.y; }

// g-pass: 512x16 tile, thread (c2 0..7, krow 0..31); 2 HFMA2 chains
#define GPASS(A) { \
    const __half2* ap = (const __half2*)((A) + goff); \
    __half2 a0 = __float2half2_rn(0.0f), a1 = __float2half2_rn(0.0f); \
    _Pragma("unroll") \
    for (int i = 0; i < 8; i++) { \
        a0 = __hfma2(vr2[2 * i],     ap[(2 * i) * 256],     a0); \
        a1 = __hfma2(vr2[2 * i + 1], ap[(2 * i + 1) * 256], a1); \
    } \
    float2 gf = __half22float2(__hadd2(a0, a1)); \
    spg[krow * NB + 2 * c2]     = gf.x; \
    spg[krow * NB + 2 * c2 + 1] = gf.y; }

// x update for the group's block j (threads tg<NB)
#define UPDATE(j) { \
    float g0 = 0.0f, g1 = 0.0f, g2 = 0.0f, g3 = 0.0f; \
    _Pragma("unroll") \
    for (int k = 0; k < 8; k++) { \
        g0 += spg[(4 * k) * NB + tg]; \
        g1 += spg[(4 * k + 1) * NB + tg]; \
        g2 += spg[(4 * k + 2) * NB + tg]; \
        g3 += spg[(4 * k + 3) * NB + tg]; \
    } \
    float g   = (g0 + g1) + (g2 + g3); \
    int   col = (grp * NGBLK + (j)) * NB + tg; \
    float xo  = sx[col]; \
    float den = __fadd_rn(1.0f, __fmul_rn(C_SCALE, g)); \
    float lr  = __fdiv_rn(C_ALPHA, den); \
    float xn  = fmaxf(__fsub_rn(xo, __fmul_rn(lr, g)), 0.0f); \
    sx[col] = xn; \
    sxhg[tg] = __float2half_rn(xn); }

// per-sweep finalize (full CTA): exchange y halves, viol, total, vr2 reload
#define FINALIZE() { \
    sypg[tg]       = yacc0; \
    sypg[256 + tg] = yacc1; \
    __syncthreads(); \
    float v = fmaxf(__fadd_rn(syp[tid] + syp[512 + tid], -breg), 0.0f); \
    sviol[tid] = v; \
    float t = v; \
    _Pragma("unroll") \
    for (int o = 16; o > 0; o >>= 1) t += __shfl_down_sync(0xffffffffu, t, o); \
    if ((tid & 31) == 0) sred[tid >> 5] = t; \
    __syncthreads(); \
    if (tid < 32) { \
        float w = (tid < 16) ? sred[tid] : 0.0f; \
        _Pragma("unroll") \
        for (int o = 8; o > 0; o >>= 1) w += __shfl_down_sync(0xffffffffu, w, o); \
        if (tid == 0) sred[16] = w; \
    } \
    __syncthreads(); \
    total = sred[16]; \
    _Pragma("unroll") \
    for (int i = 0; i < 16; i++) \
        vr2[i] = __half2half2(__float2half_rn(sviol[krow + 32 * i])); \
    yacc0 = 0.0f; yacc1 = 0.0f; }

__global__ __launch_bounds__(TPB, 2)
void lva_kernel(const float* __restrict__ xin,
                const float* __restrict__ bin,
                float* __restrict__ xout) {
    const int p    = blockIdx.x;
    const int tid  = threadIdx.x;
    const int grp  = tid >> 8;            // 0 or 1
    const int tg   = tid & 255;           // thread-in-group
    const int barid = 1 + grp;

    // group-private tile ring (3 x 16KB)
    __half* sAg  = smh + (size_t)grp * 3 * TILE_H;
    float* sx    = (float*)(smh + 6 * TILE_H);   // 512
    float* sviol = sx + NN;                      // 512
    float* syp   = sviol + MM;                   // 1024 ([2 groups][512] y partials)
    float* spart = syp + 1024;                   // 1024 ([2 groups][32 phases][16 cols])
    float* sred  = spart + 1024;                 // 32
    __half* sxh  = (__half*)(sred + 32);         // 32 ([2 groups][16])

    float*  spg  = spart + grp * 512;
    float*  sypg = syp + grp * 512;
    __half* sxhg = sxh + grp * NB;

    // this group's 16 contiguous tiles
    const __half* Tg = d_At + (size_t)p * (MM * NN) + (size_t)grp * NGBLK * TILE_H;

    unsigned long long pol;
    if (p < NRES)
        asm("createpolicy.fractional.L2::evict_last.b64 %0, 1.0;" : "=l"(pol));
    else
        asm("createpolicy.fractional.L2::evict_first.b64 %0, 1.0;" : "=l"(pol));

    sx[tid] = xin[p * NN + tid];
    const float breg = bin[p * MM + tid];
    __syncthreads();

    load_tile_g(sAg, Tg, tg, pol);
    load_tile_g(sAg + TILE_H, Tg + TILE_H, tg, pol);
    unsigned gl = 2, gcnt = 0;        // group-local tile counters

    const int c2   = tg & 7;                  // g-pass col pair (cols 2c2,2c2+1)
    const int krow = tg >> 3;                 // g-pass row phase (0..31)
    const int goff = krow * NB + (((c2 >> 2) ^ ((krow >> 2) & 1)) << 3) + ((c2 & 3) << 1);
    const int q    = (tg >> 2) & 1;           // y-pass swizzle key (rows tg, tg+256 share it)

    __half2 vr2[16];
    float yacc0 = 0.0f, yacc1 = 0.0f;
    float total;

    // ---------- initial sweep: y = A @ x (fp32 x) ----------
    for (int j = 0; j < NGBLK; j++) {
        cp_wait1();
        GBAR();
        load_tile_g(sAg + (gl % 3) * TILE_H, Tg + (size_t)(gl & 15) * TILE_H, tg, pol); gl++;
        const __half* A = sAg + (gcnt % 3) * TILE_H; gcnt++;
        const float4* xq = (const float4*)(sx + (grp * NGBLK + j) * NB);
        YROW32(yacc0, A + tg * NB, xq);
        YROW32(yacc1, A + (tg + 256) * NB, xq);
    }
    FINALIZE();

    // ---------- iterate sweeps 1..50: per block [gbar] {g(j) || y(j-1)} [gbar] {prefetch; upd(j)} ----------
    int it = 0;
    while (it < MAX_UPD - 1 && total >= C_DELTA) {
        const __half* Aprev = sAg;     // dummy; unused at j=0

        for (int j = 0; j < NGBLK; j++) {
            cp_wait1();
            GBAR();                    // tile j ready; upd(j-1) visible (group scope)
            const __half* A = sAg + (gcnt % 3) * TILE_H;

            GPASS(A);
            if (j > 0) {
                YROWH(yacc0, Aprev + tg * NB);
                YROWH(yacc1, Aprev + (tg + 256) * NB);
            }
            GBAR();                    // g partials done; tile j-1 free; sxhg consumed

            load_tile_g(sAg + (gl % 3) * TILE_H, Tg + (size_t)(gl & 15) * TILE_H, tg, pol); gl++;
            if (tg < NB) UPDATE(j);
            Aprev = A; gcnt++;
        }

        GBAR();                        // upd(15) visible to group
        YROWH(yacc0, Aprev + tg * NB);           // y(15)
        YROWH(yacc1, Aprev + (tg + 256) * NB);

        FINALIZE();
        it++;
    }

    // ---------- peeled 51st sweep: g + update only ----------
    if (total >= C_DELTA) {
        for (int j = 0; j < NGBLK; j++) {
            cp_wait1();
            GBAR();
            const __half* A = sAg + (gcnt % 3) * TILE_H;
            GPASS(A);
            GBAR();
            load_tile_g(sAg + (gl % 3) * TILE_H, Tg + (size_t)(gl & 15) * TILE_H, tg, pol); gl++;
            if (tg < NB) UPDATE(j);
            gcnt++;
        }
    }

    cp_wait0();                        // drain speculative loads
    __syncthreads();                   // all groups' sx updates visible
    xout[p * NN + tid] = sx[tid];
}

extern "C" void kernel_launch(void* const* d_in, const int* in_sizes, int n_in,
                              void* d_out, int out_size) {
    // metadata order: x [B,S,N], A [B,S,M,N], b [B,S,M]
    const float* x = (const float*)d_in[0];
    const float* A = (const float*)d_in[1];
    const float* b = (const float*)d_in[2];
    float* out = (float*)d_out;

    if (n_in == 3 && in_sizes[0] > in_sizes[1]) {   // defensive: A is the big one
        A = (const float*)d_in[0];
        x = (const float*)d_in[1];
    }

    int nprob = out_size / NN;   // 256

    retile_kernel<<<nprob, TPB>>>(A);

    size_t smem_bytes = (size_t)(6 * TILE_H) * sizeof(__half)
                      + (size_t)(NN + MM + 1024 + 1024 + 32) * sizeof(float)
                      + 32 * sizeof(__half);
    cudaFuncSetAttribute(lva_kernel, cudaFuncAttributeMaxDynamicSharedMemorySize,
                         (int)smem_bytes);
    lva_kernel<<<nprob, TPB, smem_bytes>>>(x, b, out);
}